// round 6
// baseline (speedup 1.0000x reference)
#include <cuda_runtime.h>
#include <cuda_bf16.h>
#include <cstdint>
#include <cstring>

// einsum('bis,ie->bse') via mma.sync bf16 3-term split, software-pipelined.
//   inputs    [B=64, I=64, S=4096] f32
//   embedding [I=64, E=64]         f32
//   out       [B=64, S=4096, E=64] f32
//
// D = Ahi*Bhi + Ahi*Blo + Alo*Bhi  (bf16 operands, fp32 accumulate)
// rel err ~3.4e-6 (validated).
//
// vs round 5: A global loads for iteration ks+1 are issued before the
// MMA/LDS block of iteration ks (register prefetch, no extra traffic);
// B-fragment LDS inlined per n-tile to free registers for the prefetch
// buffer inside the 128-reg / 2-CTA-per-SM budget.

#define BATCH 64
#define ISZ   64
#define SEQ   4096
#define ESZ   64
#define MTILE 256        // s per CTA
#define THREADS 256

#define BS_STRIDE 72     // u32 words per k2-row; conflict-free fragment reads
#define SMEM_BH_OFF 0
#define SMEM_BL_OFF (32 * BS_STRIDE * 4)
#define SMEM_TOTAL  (2 * 32 * BS_STRIDE * 4)   // 18432 B

__device__ __forceinline__ uint32_t pack_bf2(float a, float b) {
    __nv_bfloat162 h = __floats2bfloat162_rn(a, b);  // .x -> low 16 bits
    uint32_t u; memcpy(&u, &h, 4);
    return u;
}

__device__ __forceinline__ void split_pair(float xa, float xb,
                                           uint32_t& hi, uint32_t& lo) {
    hi = pack_bf2(xa, xb);
    __nv_bfloat162 hv; memcpy(&hv, &hi, 4);
    lo = pack_bf2(xa - __bfloat162float(hv.x), xb - __bfloat162float(hv.y));
}

#define MMA_BF16(d, a0, a1, a2, a3, b0, b1) \
    asm volatile("mma.sync.aligned.m16n8k16.row.col.f32.bf16.bf16.f32 " \
        "{%0,%1,%2,%3}, {%4,%5,%6,%7}, {%8,%9}, {%0,%1,%2,%3};" \
        : "+f"((d)[0]), "+f"((d)[1]), "+f"((d)[2]), "+f"((d)[3]) \
        : "r"(a0), "r"(a1), "r"(a2), "r"(a3), "r"(b0), "r"(b1))

// Load the 16 A values for one ks iteration (both m-tiles).
#define LOAD_A(buf, base, ka) do { \
    const float* _P0 = (base) + (size_t)((ka)    ) * SEQ; \
    const float* _P1 = (base) + (size_t)((ka) + 1) * SEQ; \
    const float* _P8 = (base) + (size_t)((ka) + 8) * SEQ; \
    const float* _P9 = (base) + (size_t)((ka) + 9) * SEQ; \
    (buf)[0]  = _P0[0];  (buf)[1]  = _P1[0];  (buf)[2]  = _P0[8];  (buf)[3]  = _P1[8]; \
    (buf)[4]  = _P8[0];  (buf)[5]  = _P9[0];  (buf)[6]  = _P8[8];  (buf)[7]  = _P9[8]; \
    (buf)[8]  = _P0[16]; (buf)[9]  = _P1[16]; (buf)[10] = _P0[24]; (buf)[11] = _P1[24]; \
    (buf)[12] = _P8[16]; (buf)[13] = _P9[16]; (buf)[14] = _P8[24]; (buf)[15] = _P9[24]; \
} while (0)

__global__ __launch_bounds__(THREADS, 2)
void embed_mma_kernel(const float* __restrict__ in,
                      const float* __restrict__ emb,
                      float* __restrict__ out)
{
    extern __shared__ char smem[];
    uint32_t* Bh = reinterpret_cast<uint32_t*>(smem + SMEM_BH_OFF);
    uint32_t* Bl = reinterpret_cast<uint32_t*>(smem + SMEM_BL_OFF);

    const int t = threadIdx.x;
    const int b     = blockIdx.x >> 4;      // 16 s-tiles per batch
    const int stile = blockIdx.x & 15;
    const int s0    = stile * MTILE;

    const int w    = t >> 5;
    const int lane = t & 31;
    const int r  = lane >> 2;     // 0..7
    const int cq = lane & 3;      // 0..3

    // warp covers s rows [s0+32w, +32): m-tile 0 at +0, m-tile 1 at +16
    const float* Ab = in + (size_t)b * (ISZ * SEQ) + s0 + 32 * w + r;

    // ---- issue first A prefetch BEFORE B staging so LDG latency overlaps
    //      the staging work ----
    float cur[16];
    LOAD_A(cur, Ab, 2 * cq);      // ks = 0: ka = 0*16 + 2*cq

    // ---- stage B: read emb f32, split hi/lo, pack k-pairs ----
    {
        #pragma unroll
        for (int j = 0; j < 8; ++j) {
            int idx = j * THREADS + t;      // 0..2047
            int k2 = idx >> 6, e = idx & 63;
            float x0 = emb[(2 * k2) * ESZ + e];
            float x1 = emb[(2 * k2 + 1) * ESZ + e];
            uint32_t hp, lp;
            split_pair(x0, x1, hp, lp);
            Bh[k2 * BS_STRIDE + e] = hp;
            Bl[k2 * BS_STRIDE + e] = lp;
        }
    }
    __syncthreads();

    float acc[2][8][4];
    #pragma unroll
    for (int mt = 0; mt < 2; ++mt)
        #pragma unroll
        for (int nt = 0; nt < 8; ++nt)
            #pragma unroll
            for (int q = 0; q < 4; ++q) acc[mt][nt][q] = 0.0f;

    #pragma unroll
    for (int ks = 0; ks < 4; ++ks) {
        // ---- prefetch A for next iteration before any compute ----
        float nxt[16];
        if (ks < 3)
            LOAD_A(nxt, Ab, (ks + 1) * 16 + 2 * cq);

        // ---- split current A into fragments ----
        uint32_t a0h[2], a1h[2], a2h[2], a3h[2];
        uint32_t a0l[2], a1l[2], a2l[2], a3l[2];
        split_pair(cur[0],  cur[1],  a0h[0], a0l[0]);
        split_pair(cur[2],  cur[3],  a1h[0], a1l[0]);
        split_pair(cur[4],  cur[5],  a2h[0], a2l[0]);
        split_pair(cur[6],  cur[7],  a3h[0], a3l[0]);
        split_pair(cur[8],  cur[9],  a0h[1], a0l[1]);
        split_pair(cur[10], cur[11], a1h[1], a1l[1]);
        split_pair(cur[12], cur[13], a2h[1], a2l[1]);
        split_pair(cur[14], cur[15], a3h[1], a3l[1]);

        const uint32_t* bh0 = Bh + (ks * 8 + cq) * BS_STRIDE + r;
        const uint32_t* bh1 = Bh + (ks * 8 + cq + 4) * BS_STRIDE + r;
        const uint32_t* bl0 = Bl + (ks * 8 + cq) * BS_STRIDE + r;
        const uint32_t* bl1 = Bl + (ks * 8 + cq + 4) * BS_STRIDE + r;

        // ---- per n-tile: inline B loads + 6 MMAs ----
        #pragma unroll
        for (int nt = 0; nt < 8; ++nt) {
            const uint32_t b0h = bh0[nt * 8];
            const uint32_t b1h = bh1[nt * 8];
            const uint32_t b0l = bl0[nt * 8];
            const uint32_t b1l = bl1[nt * 8];
            MMA_BF16(acc[0][nt], a0h[0], a1h[0], a2h[0], a3h[0], b0h, b1h);
            MMA_BF16(acc[0][nt], a0h[0], a1h[0], a2h[0], a3h[0], b0l, b1l);
            MMA_BF16(acc[0][nt], a0l[0], a1l[0], a2l[0], a3l[0], b0h, b1h);
            MMA_BF16(acc[1][nt], a0h[1], a1h[1], a2h[1], a3h[1], b0h, b1h);
            MMA_BF16(acc[1][nt], a0h[1], a1h[1], a2h[1], a3h[1], b0l, b1l);
            MMA_BF16(acc[1][nt], a0l[1], a1l[1], a2l[1], a3l[1], b0h, b1h);
        }

        #pragma unroll
        for (int j = 0; j < 16; ++j) cur[j] = nxt[j];
    }

    // ---- epilogue ----
    #pragma unroll
    for (int mt = 0; mt < 2; ++mt) {
        const size_t srow = (size_t)b * SEQ + s0 + 32 * w + 16 * mt + r;
        float* orow  = out + srow * ESZ;
        float* orow8 = out + (srow + 8) * ESZ;
        #pragma unroll
        for (int nt = 0; nt < 8; ++nt) {
            *reinterpret_cast<float2*>(orow  + nt * 8 + 2 * cq) =
                make_float2(acc[mt][nt][0], acc[mt][nt][1]);
            *reinterpret_cast<float2*>(orow8 + nt * 8 + 2 * cq) =
                make_float2(acc[mt][nt][2], acc[mt][nt][3]);
        }
    }
}

extern "C" void kernel_launch(void* const* d_in, const int* in_sizes, int n_in,
                              void* d_out, int out_size)
{
    const float* in  = (const float*)d_in[0];   // [64, 64, 4096]
    const float* emb = (const float*)d_in[1];   // [64, 64]
    float* out = (float*)d_out;                 // [64, 4096, 64]

    const int blocks = BATCH * (SEQ / MTILE);   // 64 * 16 = 1024
    embed_mma_kernel<<<blocks, THREADS, SMEM_TOTAL>>>(in, emb, out);
}